// round 9
// baseline (speedup 1.0000x reference)
#include <cuda_runtime.h>
#include <cuda_bf16.h>
#include <cstdint>

// Problem constants (DiffnapsNet_42030549959310)
#define BV 4096   // batch
#define DV 8192   // data dim
#define HV 4096   // hidden
#define LV 128    // labels

#define FP8_ONE 0x38u     // e4m3 1.0
#define BF16_ONE 0x3F80u  // bf16 1.0

// ---------------------------------------------------------------------------
// Scratch (device globals; no allocation allowed)
// ---------------------------------------------------------------------------
__device__ __align__(16) uint8_t  g_x8[(size_t)BV * DV];    // [B][D] e4m3
__device__ __align__(16) uint8_t  g_w8[(size_t)HV * DV];    // [H][D] e4m3
__device__ __align__(16) uint8_t  g_wT8[(size_t)DV * HV];   // [D][H] e4m3
__device__ __align__(16) uint8_t  g_z8[(size_t)BV * HV];    // [B][H] e4m3
__device__ __align__(16) uint16_t g_zbf[(size_t)BV * HV];   // [B][H] bf16
__device__ __align__(16) uint16_t g_whi[(size_t)LV * HV];   // [L][H] bf16 hi
__device__ __align__(16) uint16_t g_wlo[(size_t)LV * HV];   // [L][H] bf16 lo

// ---------------------------------------------------------------------------
// PTX helpers (family-compatible: sm_80/89 features only)
// ---------------------------------------------------------------------------
__device__ __forceinline__ uint32_t smem_u32(const void* p) {
    uint32_t a;
    asm("{ .reg .u64 t; cvta.to.shared.u64 t, %1; cvt.u32.u64 %0, t; }"
        : "=r"(a) : "l"(p));
    return a;
}
__device__ __forceinline__ void cp16(uint32_t dst, const void* src) {
    asm volatile("cp.async.cg.shared.global [%0], [%1], 16;"
                 :: "r"(dst), "l"(src) : "memory");
}
#define CP_COMMIT() asm volatile("cp.async.commit_group;" ::: "memory")
#define CP_WAIT(n)  asm volatile("cp.async.wait_group %0;" :: "n"(n) : "memory")

__device__ __forceinline__ void ldm_x4(uint32_t (&r)[4], uint32_t addr) {
    asm volatile("ldmatrix.sync.aligned.m8n8.x4.shared.b16 {%0,%1,%2,%3}, [%4];"
                 : "=r"(r[0]), "=r"(r[1]), "=r"(r[2]), "=r"(r[3]) : "r"(addr));
}
__device__ __forceinline__ void mma_fp8(float (&c)[4], const uint32_t (&a)[4],
                                        uint32_t b0, uint32_t b1) {
    asm volatile(
        "mma.sync.aligned.m16n8k32.row.col.f32.e4m3.e4m3.f32 "
        "{%0,%1,%2,%3}, {%4,%5,%6,%7}, {%8,%9}, {%0,%1,%2,%3};"
        : "+f"(c[0]), "+f"(c[1]), "+f"(c[2]), "+f"(c[3])
        : "r"(a[0]), "r"(a[1]), "r"(a[2]), "r"(a[3]), "r"(b0), "r"(b1));
}
__device__ __forceinline__ void mma_bf16(float (&c)[4], const uint32_t (&a)[4],
                                         uint32_t b0, uint32_t b1) {
    asm volatile(
        "mma.sync.aligned.m16n8k16.row.col.f32.bf16.bf16.f32 "
        "{%0,%1,%2,%3}, {%4,%5,%6,%7}, {%8,%9}, {%0,%1,%2,%3};"
        : "+f"(c[0]), "+f"(c[1]), "+f"(c[2]), "+f"(c[3])
        : "r"(a[0]), "r"(a[1]), "r"(a[2]), "r"(a[3]), "r"(b0), "r"(b1));
}

// ---------------------------------------------------------------------------
// Conversions
// ---------------------------------------------------------------------------
__global__ void cvt_fp8_kernel(const float* __restrict__ src,
                               uint32_t* __restrict__ dst, int n4) {
    int i = blockIdx.x * blockDim.x + threadIdx.x;
    if (i < n4) {
        float4 v = ((const float4*)src)[i];
        uint32_t w = (v.x > 0.5f ? FP8_ONE : 0u) | (v.y > 0.5f ? FP8_ONE << 8 : 0u) |
                     (v.z > 0.5f ? FP8_ONE << 16 : 0u) | (v.w > 0.5f ? FP8_ONE << 24 : 0u);
        dst[i] = w;
    }
}

// One pass over enc_weight -> both w8 (row-major) and wT8 (transposed).
__global__ void cvt_w_both_kernel(const float* __restrict__ w,
                                  uint8_t* __restrict__ w8,
                                  uint8_t* __restrict__ wT) {
    int d  = blockIdx.x * blockDim.x + threadIdx.x;  // 0..DV-1
    int hw = blockIdx.y;                             // 0..HV/32-1
    const float* col = w + (size_t)hw * 32 * DV + d;
    uint32_t wd[8];
#pragma unroll
    for (int q = 0; q < 8; q++) {
        uint32_t v = 0;
#pragma unroll
        for (int c = 0; c < 4; c++) {
            bool b = col[(size_t)(q * 4 + c) * DV] > 0.5f;
            if (b) v |= FP8_ONE << (c * 8);
            w8[(size_t)(hw * 32 + q * 4 + c) * DV + d] = b ? (uint8_t)FP8_ONE : 0;
        }
        wd[q] = v;
    }
    uint4* dst = (uint4*)(wT + (size_t)d * HV + hw * 32);
    dst[0] = make_uint4(wd[0], wd[1], wd[2], wd[3]);
    dst[1] = make_uint4(wd[4], wd[5], wd[6], wd[7]);
}

// Exact bf16 split of classifier weights: w = hi + lo
__global__ void cvt_wsplit_kernel(const float* __restrict__ w,
                                  uint16_t* __restrict__ whi,
                                  uint16_t* __restrict__ wlo, int n) {
    int i = blockIdx.x * blockDim.x + threadIdx.x;
    if (i < n) {
        float v = w[i];
        __nv_bfloat16 h = __float2bfloat16(v);
        float r = v - __bfloat162float(h);
        __nv_bfloat16 l = __float2bfloat16(r);
        whi[i] = *(uint16_t*)&h;
        wlo[i] = *(uint16_t*)&l;
    }
}

// ---------------------------------------------------------------------------
// FP8 mma.sync GEMM: 512 threads (16 warps, 4x4), warp tile 32x32,
// 4-stage cp.async ring, one barrier per 64B K-chunk.
//   cnt[m][n] = sum_k A[m][k]*B[n][k]  (exact counts, fp32 accum)
//   Cf = (cnt + bias[n] > 1) ? 1 : 0;  optionally also e4m3 + bf16 copies.
// Smem row stride 80B -> ldmatrix conflict-free without swizzle.
// ---------------------------------------------------------------------------
#define LDT 80
#define ATILE (128 * LDT)          // 10240
#define STAGE_B (2 * ATILE)        // 20480 (A then B)
#define GEMM_SMEM (4 * STAGE_B)    // 81920

template <int KB, bool WRITE_AUX>
__global__ __launch_bounds__(512, 1) void fp8_mma_gemm_kernel(
    const uint8_t* __restrict__ A, const uint8_t* __restrict__ Bm,
    const float* __restrict__ bias, float* __restrict__ Cf,
    uint8_t* __restrict__ C8, uint16_t* __restrict__ Cbf, int Ntot) {
    constexpr int NCH = KB / 64;
    extern __shared__ __align__(16) uint8_t smem[];
    const uint32_t s0 = smem_u32(smem);

    const int tid  = threadIdx.x;
    const int lane = tid & 31;
    const int wid  = tid >> 5;
    const int wm   = wid & 3;    // m: wm*32
    const int wn   = wid >> 2;   // n: wn*32
    const int m0   = blockIdx.y * 128;
    const int n0   = blockIdx.x * 128;

    // global->smem cp.async mapping: 1 uint4 per tile per thread
    const int gr = tid >> 2;        // 0..127
    const int gq = (tid & 3) * 16;  // 16B chunk in 64B row
    const uint8_t* gA = A + (size_t)(m0 + gr) * KB + gq;
    const uint8_t* gB = Bm + (size_t)(n0 + gr) * KB + gq;
    const uint32_t wOff = gr * LDT + gq;

    // ldmatrix read addresses (layout verified in R7/R8)
    const uint32_t rdA0 = s0 +
        (wm * 32 + (lane & 7) + ((lane >> 3) & 1) * 8) * LDT + (lane >> 4) * 16;
    const uint32_t rdB0 = s0 + ATILE +
        (wn * 32 + (lane & 7) + ((lane >> 4) & 1) * 8) * LDT + ((lane >> 3) & 1) * 16;

    float acc[2][4][4];
#pragma unroll
    for (int mt = 0; mt < 2; mt++)
#pragma unroll
        for (int nt = 0; nt < 4; nt++)
#pragma unroll
            for (int c = 0; c < 4; c++) acc[mt][nt][c] = 0.0f;

    auto issue = [&](int ch, int st) {
        const uint32_t base = s0 + st * STAGE_B;
        cp16(base + wOff, gA + ch * 64);
        cp16(base + ATILE + wOff, gB + ch * 64);
        CP_COMMIT();
    };
    issue(0, 0);
    issue(1, 1);
    issue(2, 2);

    for (int ch = 0; ch < NCH; ch++) {
        if (ch + 2 < NCH)      { CP_WAIT(2); }
        else if (ch + 1 < NCH) { CP_WAIT(1); }
        else                   { CP_WAIT(0); }
        __syncthreads();   // chunk ch visible; stage (ch+3)%4's old reads done
        if (ch + 3 < NCH) issue(ch + 3, (ch + 3) & 3);

        const uint32_t off = (uint32_t)(ch & 3) * STAGE_B;
#pragma unroll
        for (int ks = 0; ks < 2; ks++) {
            uint32_t af[2][4];
            ldm_x4(af[0], rdA0 + off + ks * 32);
            ldm_x4(af[1], rdA0 + off + 16 * LDT + ks * 32);
            uint32_t bf[4][2];
#pragma unroll
            for (int nt2 = 0; nt2 < 2; nt2++) {
                uint32_t t[4];
                ldm_x4(t, rdB0 + off + nt2 * 16 * LDT + ks * 32);
                bf[2 * nt2][0] = t[0]; bf[2 * nt2][1] = t[1];
                bf[2 * nt2 + 1][0] = t[2]; bf[2 * nt2 + 1][1] = t[3];
            }
#pragma unroll
            for (int mt = 0; mt < 2; mt++)
#pragma unroll
                for (int nt = 0; nt < 4; nt++)
                    mma_fp8(acc[mt][nt], af[mt], bf[nt][0], bf[nt][1]);
        }
    }

    // epilogue: threshold with per-column bias
    {
        const int g  = lane >> 2;
        const int tg = lane & 3;
        const int rbase = m0 + wm * 32 + g;
        const int cbase = n0 + wn * 32 + tg * 2;
#pragma unroll
        for (int mt = 0; mt < 2; mt++) {
            const int r0 = rbase + mt * 16;
            const int r1 = r0 + 8;
#pragma unroll
            for (int nt = 0; nt < 4; nt++) {
                const int c = cbase + nt * 8;
                const float bx = bias[c], by = bias[c + 1];
                float v00 = (acc[mt][nt][0] + bx > 1.0f) ? 1.0f : 0.0f;
                float v01 = (acc[mt][nt][1] + by > 1.0f) ? 1.0f : 0.0f;
                float v10 = (acc[mt][nt][2] + bx > 1.0f) ? 1.0f : 0.0f;
                float v11 = (acc[mt][nt][3] + by > 1.0f) ? 1.0f : 0.0f;
                *(float2*)(Cf + (size_t)r0 * Ntot + c) = make_float2(v00, v01);
                *(float2*)(Cf + (size_t)r1 * Ntot + c) = make_float2(v10, v11);
                if (WRITE_AUX) {
                    *(uint16_t*)(C8 + (size_t)r0 * Ntot + c) =
                        (uint16_t)((v00 != 0.0f ? FP8_ONE : 0u) |
                                   (v01 != 0.0f ? FP8_ONE << 8 : 0u));
                    *(uint16_t*)(C8 + (size_t)r1 * Ntot + c) =
                        (uint16_t)((v10 != 0.0f ? FP8_ONE : 0u) |
                                   (v11 != 0.0f ? FP8_ONE << 8 : 0u));
                    *(uint32_t*)(Cbf + (size_t)r0 * Ntot + c) =
                        (v00 != 0.0f ? BF16_ONE : 0u) |
                        (v01 != 0.0f ? BF16_ONE << 16 : 0u);
                    *(uint32_t*)(Cbf + (size_t)r1 * Ntot + c) =
                        (v10 != 0.0f ? BF16_ONE : 0u) |
                        (v11 != 0.0f ? BF16_ONE << 16 : 0u);
                }
            }
        }
    }
}

// ---------------------------------------------------------------------------
// Classifier via bf16 mma with exact W split (proven in R8):
//   C[b][l] = sum_h zbf[b][h] * (Whi[l][h] + Wlo[l][h])
// ---------------------------------------------------------------------------
#define CLF_T (128 * LDT)          // 10240 per tile
#define CLF_STG (3 * CLF_T)        // 30720 per stage (A, Whi, Wlo)
#define CLF_SMEM (3 * CLF_STG)     // 92160

__global__ __launch_bounds__(256) void clf_mma_kernel(
    const uint16_t* __restrict__ Z, const uint16_t* __restrict__ Whi,
    const uint16_t* __restrict__ Wlo, float* __restrict__ C) {
    constexpr int NCH = HV / 32;
    extern __shared__ __align__(16) uint8_t smem[];
    const uint32_t s0 = smem_u32(smem);

    const int tid  = threadIdx.x;
    const int lane = tid & 31;
    const int wid  = tid >> 5;
    const int wm   = wid & 3;
    const int wn   = wid >> 2;
    const int m0   = blockIdx.x * 128;

    const int gr = tid >> 2;
    const int gq = (tid & 3) * 16;
    const uint8_t* gA = (const uint8_t*)Z + ((size_t)(m0 + gr) * HV) * 2 + gq;
    const uint8_t* gH = (const uint8_t*)Whi + ((size_t)gr * HV) * 2 + gq;
    const uint8_t* gL = (const uint8_t*)Wlo + ((size_t)gr * HV) * 2 + gq;
    const uint32_t wA = s0 + gr * LDT + gq;
    const uint32_t wH = wA + CLF_T;
    const uint32_t wL = wH + CLF_T;

    const int a_row = wm * 32 + (lane & 7) + ((lane >> 3) & 1) * 8;
    const int a_qc  = (lane >> 4);
    const int b_row = wn * 64 + (lane & 7) + ((lane >> 4) & 1) * 8;
    const int b_qc  = (lane >> 3) & 1;
    const uint32_t rdA0 = s0 + a_row * LDT + a_qc * 16;
    const uint32_t rdH0 = s0 + CLF_T + b_row * LDT + b_qc * 16;
    const uint32_t rdL0 = rdH0 + CLF_T;

    float acc[2][8][4];
#pragma unroll
    for (int mt = 0; mt < 2; mt++)
#pragma unroll
        for (int nt = 0; nt < 8; nt++)
#pragma unroll
            for (int c = 0; c < 4; c++) acc[mt][nt][c] = 0.0f;

    auto issue = [&](int ch, int st) {
        const uint32_t off = st * CLF_STG;
        const int kc = ch * 64;
        cp16(wA + off, gA + kc);
        cp16(wA + off + 64 * LDT, gA + (size_t)64 * HV * 2 + kc);
        cp16(wH + off, gH + kc);
        cp16(wH + off + 64 * LDT, gH + (size_t)64 * HV * 2 + kc);
        cp16(wL + off, gL + kc);
        cp16(wL + off + 64 * LDT, gL + (size_t)64 * HV * 2 + kc);
        CP_COMMIT();
    };
    issue(0, 0);
    issue(1, 1);

    int st = 0, st_wr = 2;
    for (int ch = 0; ch < NCH; ch++) {
        if (ch + 1 < NCH) { CP_WAIT(1); } else { CP_WAIT(0); }
        __syncthreads();
        if (ch + 2 < NCH) {
            issue(ch + 2, st_wr);
            st_wr = (st_wr == 2) ? 0 : st_wr + 1;
        }
        const uint32_t rdA = rdA0 + st * CLF_STG;
        const uint32_t rdH = rdH0 + st * CLF_STG;
        const uint32_t rdL = rdL0 + st * CLF_STG;
#pragma unroll
        for (int ks = 0; ks < 2; ks++) {
            uint32_t af[2][4];
            ldm_x4(af[0], rdA + ks * 32);
            ldm_x4(af[1], rdA + 16 * LDT + ks * 32);
            uint32_t bh[8][2], bl[8][2];
#pragma unroll
            for (int nt2 = 0; nt2 < 4; nt2++) {
                uint32_t t[4];
                ldm_x4(t, rdH + nt2 * 16 * LDT + ks * 32);
                bh[2 * nt2][0] = t[0]; bh[2 * nt2][1] = t[1];
                bh[2 * nt2 + 1][0] = t[2]; bh[2 * nt2 + 1][1] = t[3];
                ldm_x4(t, rdL + nt2 * 16 * LDT + ks * 32);
                bl[2 * nt2][0] = t[0]; bl[2 * nt2][1] = t[1];
                bl[2 * nt2 + 1][0] = t[2]; bl[2 * nt2 + 1][1] = t[3];
            }
#pragma unroll
            for (int mt = 0; mt < 2; mt++)
#pragma unroll
                for (int nt = 0; nt < 8; nt++) {
                    mma_bf16(acc[mt][nt], af[mt], bh[nt][0], bh[nt][1]);
                    mma_bf16(acc[mt][nt], af[mt], bl[nt][0], bl[nt][1]);
                }
        }
        st = (st == 2) ? 0 : st + 1;
    }

    {
        const int g  = lane >> 2;
        const int tg = lane & 3;
        const int rbase = m0 + wm * 32 + g;
        const int cbase = wn * 64 + tg * 2;
#pragma unroll
        for (int mt = 0; mt < 2; mt++) {
            const int r0 = rbase + mt * 16;
            const int r1 = r0 + 8;
#pragma unroll
            for (int nt = 0; nt < 8; nt++) {
                const int c = cbase + nt * 8;
                *(float2*)(C + (size_t)r0 * LV + c) =
                    make_float2(acc[mt][nt][0], acc[mt][nt][1]);
                *(float2*)(C + (size_t)r1 * LV + c) =
                    make_float2(acc[mt][nt][2], acc[mt][nt][3]);
            }
        }
    }
}

// ---------------------------------------------------------------------------
// Launch.  Output layout: [output (B*D) | classification (B*L) | z (B*H)].
// ---------------------------------------------------------------------------
extern "C" void kernel_launch(void* const* d_in, const int* in_sizes, int n_in,
                              void* d_out, int out_size) {
    const float* x     = (const float*)d_in[0];
    const float* w     = (const float*)d_in[1];
    const float* bias0 = (const float*)d_in[2];
    const float* bias3 = (const float*)d_in[3];
    const float* clf   = (const float*)d_in[4];

    float* out        = (float*)d_out;
    float* out_output = out;
    float* out_class  = out + (size_t)BV * DV;
    float* out_z      = out + (size_t)BV * DV + (size_t)BV * LV;

    uint8_t *x8, *w8, *wT8, *z8;
    uint16_t *zbf, *whi, *wlo;
    cudaGetSymbolAddress((void**)&x8, g_x8);
    cudaGetSymbolAddress((void**)&w8, g_w8);
    cudaGetSymbolAddress((void**)&wT8, g_wT8);
    cudaGetSymbolAddress((void**)&z8, g_z8);
    cudaGetSymbolAddress((void**)&zbf, g_zbf);
    cudaGetSymbolAddress((void**)&whi, g_whi);
    cudaGetSymbolAddress((void**)&wlo, g_wlo);

    cudaFuncSetAttribute(fp8_mma_gemm_kernel<DV, true>,
                         cudaFuncAttributeMaxDynamicSharedMemorySize, GEMM_SMEM);
    cudaFuncSetAttribute(fp8_mma_gemm_kernel<HV, false>,
                         cudaFuncAttributeMaxDynamicSharedMemorySize, GEMM_SMEM);
    cudaFuncSetAttribute(clf_mma_kernel,
                         cudaFuncAttributeMaxDynamicSharedMemorySize, CLF_SMEM);

    // 1) conversions
    cvt_fp8_kernel<<<(BV * DV / 4) / 256, 256>>>(x, (uint32_t*)x8, BV * DV / 4);
    cvt_w_both_kernel<<<dim3(DV / 256, HV / 32), 256>>>(w, w8, wT8);
    cvt_wsplit_kernel<<<(LV * HV) / 256, 256>>>(clf, whi, wlo, LV * HV);

    // 2) GEMM1: z = (x @ wb^T + bias0 > 1); emits float + e4m3 + bf16 copies
    fp8_mma_gemm_kernel<DV, true>
        <<<dim3(HV / 128, BV / 128), 512, GEMM_SMEM>>>(x8, w8, bias0, out_z, z8,
                                                       zbf, HV);

    // 3) GEMM2: output = (z @ wb + bias3 > 1)
    fp8_mma_gemm_kernel<HV, false>
        <<<dim3(DV / 128, BV / 128), 512, GEMM_SMEM>>>(z8, wT8, bias3, out_output,
                                                       nullptr, nullptr, DV);

    // 4) classification = z @ clf^T  (bf16 split, fp32 accum)
    clf_mma_kernel<<<BV / 128, 256, CLF_SMEM>>>(zbf, whi, wlo, out_class);
}

// round 10
// speedup vs baseline: 1.1075x; 1.1075x over previous
#include <cuda_runtime.h>
#include <cuda_bf16.h>
#include <cuda_fp16.h>
#include <cstdint>

// Problem constants (DiffnapsNet_42030549959310)
#define BV 4096   // batch
#define DV 8192   // data dim
#define HV 4096   // hidden
#define LV 128    // labels

#define FP8_ONE 0x38u     // e4m3 1.0
#define BF16_ONE 0x3F80u  // bf16 1.0

// ---------------------------------------------------------------------------
// Scratch (device globals; no allocation allowed)
// ---------------------------------------------------------------------------
__device__ __align__(16) uint8_t  g_x8[(size_t)BV * DV];    // [B][D] e4m3
__device__ __align__(16) uint8_t  g_w8[(size_t)HV * DV];    // [H][D] e4m3
__device__ __align__(16) uint8_t  g_wT8[(size_t)DV * HV];   // [D][H] e4m3
__device__ __align__(16) uint8_t  g_z8[(size_t)BV * HV];    // [B][H] e4m3
__device__ __align__(16) uint16_t g_zbf[(size_t)BV * HV];   // [B][H] bf16
__device__ __align__(16) uint16_t g_whi[(size_t)LV * HV];   // [L][H] bf16 hi
__device__ __align__(16) uint16_t g_wlo[(size_t)LV * HV];   // [L][H] bf16 lo

// ---------------------------------------------------------------------------
// PTX helpers (family-compatible: sm_80/89 features only)
// ---------------------------------------------------------------------------
__device__ __forceinline__ uint32_t smem_u32(const void* p) {
    uint32_t a;
    asm("{ .reg .u64 t; cvta.to.shared.u64 t, %1; cvt.u32.u64 %0, t; }"
        : "=r"(a) : "l"(p));
    return a;
}
__device__ __forceinline__ void cp16(uint32_t dst, const void* src) {
    asm volatile("cp.async.cg.shared.global [%0], [%1], 16;"
                 :: "r"(dst), "l"(src) : "memory");
}
#define CP_COMMIT() asm volatile("cp.async.commit_group;" ::: "memory")
#define CP_WAIT(n)  asm volatile("cp.async.wait_group %0;" :: "n"(n) : "memory")

__device__ __forceinline__ void ldm_x4(uint32_t (&r)[4], uint32_t addr) {
    asm volatile("ldmatrix.sync.aligned.m8n8.x4.shared.b16 {%0,%1,%2,%3}, [%4];"
                 : "=r"(r[0]), "=r"(r[1]), "=r"(r[2]), "=r"(r[3]) : "r"(addr));
}
// fp8 x fp8 -> fp16 accumulator (2 C regs): exact for integer counts <= 2048;
// larger counts stay >> threshold so no threshold decision can flip.
__device__ __forceinline__ void mma_fp8_h(uint32_t (&c)[2], const uint32_t (&a)[4],
                                          uint32_t b0, uint32_t b1) {
    asm volatile(
        "mma.sync.aligned.m16n8k32.row.col.f16.e4m3.e4m3.f16 "
        "{%0,%1}, {%2,%3,%4,%5}, {%6,%7}, {%0,%1};"
        : "+r"(c[0]), "+r"(c[1])
        : "r"(a[0]), "r"(a[1]), "r"(a[2]), "r"(a[3]), "r"(b0), "r"(b1));
}
__device__ __forceinline__ void mma_bf16(float (&c)[4], const uint32_t (&a)[4],
                                         uint32_t b0, uint32_t b1) {
    asm volatile(
        "mma.sync.aligned.m16n8k16.row.col.f32.bf16.bf16.f32 "
        "{%0,%1,%2,%3}, {%4,%5,%6,%7}, {%8,%9}, {%0,%1,%2,%3};"
        : "+f"(c[0]), "+f"(c[1]), "+f"(c[2]), "+f"(c[3])
        : "r"(a[0]), "r"(a[1]), "r"(a[2]), "r"(a[3]), "r"(b0), "r"(b1));
}

// ---------------------------------------------------------------------------
// Conversions
// ---------------------------------------------------------------------------
__global__ void cvt_fp8_kernel(const float* __restrict__ src,
                               uint32_t* __restrict__ dst, int n4) {
    int i = blockIdx.x * blockDim.x + threadIdx.x;
    if (i < n4) {
        float4 v = ((const float4*)src)[i];
        uint32_t w = (v.x > 0.5f ? FP8_ONE : 0u) | (v.y > 0.5f ? FP8_ONE << 8 : 0u) |
                     (v.z > 0.5f ? FP8_ONE << 16 : 0u) | (v.w > 0.5f ? FP8_ONE << 24 : 0u);
        dst[i] = w;
    }
}

// One pass over enc_weight -> both w8 (row-major) and wT8 (transposed).
__global__ void cvt_w_both_kernel(const float* __restrict__ w,
                                  uint8_t* __restrict__ w8,
                                  uint8_t* __restrict__ wT) {
    int d  = blockIdx.x * blockDim.x + threadIdx.x;  // 0..DV-1
    int hw = blockIdx.y;                             // 0..HV/32-1
    const float* col = w + (size_t)hw * 32 * DV + d;
    uint32_t wd[8];
#pragma unroll
    for (int q = 0; q < 8; q++) {
        uint32_t v = 0;
#pragma unroll
        for (int c = 0; c < 4; c++) {
            bool b = col[(size_t)(q * 4 + c) * DV] > 0.5f;
            if (b) v |= FP8_ONE << (c * 8);
            w8[(size_t)(hw * 32 + q * 4 + c) * DV + d] = b ? (uint8_t)FP8_ONE : 0;
        }
        wd[q] = v;
    }
    uint4* dst = (uint4*)(wT + (size_t)d * HV + hw * 32);
    dst[0] = make_uint4(wd[0], wd[1], wd[2], wd[3]);
    dst[1] = make_uint4(wd[4], wd[5], wd[6], wd[7]);
}

// Exact bf16 split of classifier weights: w = hi + lo
__global__ void cvt_wsplit_kernel(const float* __restrict__ w,
                                  uint16_t* __restrict__ whi,
                                  uint16_t* __restrict__ wlo, int n) {
    int i = blockIdx.x * blockDim.x + threadIdx.x;
    if (i < n) {
        float v = w[i];
        __nv_bfloat16 h = __float2bfloat16(v);
        float r = v - __bfloat162float(h);
        __nv_bfloat16 l = __float2bfloat16(r);
        whi[i] = *(uint16_t*)&h;
        wlo[i] = *(uint16_t*)&l;
    }
}

// ---------------------------------------------------------------------------
// FP8 mma.sync GEMM, fp16 accumulators.
// CTA tile 128(M) x 256(N), 256 threads = 8 warps in 2(m) x 4(n) grid,
// warp tile 64x64 (Mt=4, Nt=8).  3-stage cp.async ring, 64B K-chunks,
// one barrier per chunk.  Smem row stride 80B -> conflict-free ldmatrix.
// Fragment traffic: 128 B/MMA (vs 256 in R9) -> smem crossbar no longer binds.
// ---------------------------------------------------------------------------
#define LDT 80
#define ATILE (128 * LDT)            // 10240
#define BTILE (256 * LDT)            // 20480
#define STAGE_B (ATILE + BTILE)      // 30720
#define GEMM_SMEM (3 * STAGE_B)      // 92160

template <int KB, bool WRITE_AUX>
__global__ __launch_bounds__(256, 2) void fp8_mma_gemm_kernel(
    const uint8_t* __restrict__ A, const uint8_t* __restrict__ Bm,
    const float* __restrict__ bias, float* __restrict__ Cf,
    uint8_t* __restrict__ C8, uint16_t* __restrict__ Cbf, int Ntot) {
    constexpr int NCH = KB / 64;
    extern __shared__ __align__(16) uint8_t smem[];
    const uint32_t s0 = smem_u32(smem);

    const int tid  = threadIdx.x;
    const int lane = tid & 31;
    const int wid  = tid >> 5;
    const int wm   = wid >> 2;   // 0..1 : m offset wm*64
    const int wn   = wid & 3;    // 0..3 : n offset wn*64
    const int m0   = blockIdx.y * 128;
    const int n0   = blockIdx.x * 256;

    // global->smem cp.async mapping
    const int cr = tid >> 2;        // 0..63
    const int cq = (tid & 3) * 16;  // 16B chunk within 64B row
    const uint8_t* gA = A + (size_t)(m0 + cr) * KB + cq;          // rows cr, cr+64
    const uint8_t* gB = Bm + (size_t)(n0 + cr) * KB + cq;         // rows cr+64p, p<4
    const uint32_t wAo = cr * LDT + cq;
    const uint32_t wBo = ATILE + cr * LDT + cq;

    // ldmatrix read bases (mapping validated in R7/R8)
    const uint32_t rdA0 = s0 +
        (wm * 64 + (lane & 7) + ((lane >> 3) & 1) * 8) * LDT + (lane >> 4) * 16;
    const uint32_t rdB0 = s0 + ATILE +
        (wn * 64 + (lane & 7) + ((lane >> 4) & 1) * 8) * LDT + ((lane >> 3) & 1) * 16;

    uint32_t acc[4][8][2];   // fp16x2 accumulators, Mt=4 x Nt=8
#pragma unroll
    for (int mt = 0; mt < 4; mt++)
#pragma unroll
        for (int nt = 0; nt < 8; nt++) { acc[mt][nt][0] = 0u; acc[mt][nt][1] = 0u; }

    auto issue = [&](int ch, int st) {
        const uint32_t base = s0 + (uint32_t)st * STAGE_B;
        const int kc = ch * 64;
#pragma unroll
        for (int p = 0; p < 2; p++)
            cp16(base + wAo + p * 64 * LDT, gA + (size_t)(p * 64) * KB + kc);
#pragma unroll
        for (int p = 0; p < 4; p++)
            cp16(base + wBo + p * 64 * LDT, gB + (size_t)(p * 64) * KB + kc);
        CP_COMMIT();
    };
    issue(0, 0);
    issue(1, 1);

    int st = 0, st_wr = 2;
    for (int ch = 0; ch < NCH; ch++) {
        if (ch + 1 < NCH) { CP_WAIT(1); } else { CP_WAIT(0); }
        __syncthreads();  // chunk ch visible; stage st_wr's previous reads done
        if (ch + 2 < NCH) {
            issue(ch + 2, st_wr);
            st_wr = (st_wr == 2) ? 0 : st_wr + 1;
        }
        const uint32_t off = (uint32_t)st * STAGE_B;
#pragma unroll
        for (int ks = 0; ks < 2; ks++) {
            uint32_t bf[8][2];
#pragma unroll
            for (int nt2 = 0; nt2 < 4; nt2++) {
                uint32_t t[4];
                ldm_x4(t, rdB0 + off + nt2 * 16 * LDT + ks * 32);
                bf[2 * nt2][0] = t[0]; bf[2 * nt2][1] = t[1];
                bf[2 * nt2 + 1][0] = t[2]; bf[2 * nt2 + 1][1] = t[3];
            }
#pragma unroll
            for (int mt = 0; mt < 4; mt++) {
                uint32_t af[4];
                ldm_x4(af, rdA0 + off + mt * 16 * LDT + ks * 32);
#pragma unroll
                for (int nt = 0; nt < 8; nt++)
                    mma_fp8_h(acc[mt][nt], af, bf[nt][0], bf[nt][1]);
            }
        }
        st = (st == 2) ? 0 : st + 1;
    }

    // epilogue: unpack fp16 counts, threshold with per-column bias
    {
        const int g  = lane >> 2;
        const int tg = lane & 3;
        const int cbase = n0 + wn * 64 + tg * 2;
#pragma unroll
        for (int mt = 0; mt < 4; mt++) {
            const int r0 = m0 + wm * 64 + mt * 16 + g;
            const int r1 = r0 + 8;
#pragma unroll
            for (int nt = 0; nt < 8; nt++) {
                const int c = cbase + nt * 8;
                const float bx = bias[c], by = bias[c + 1];
                __half2 h0 = *(__half2*)&acc[mt][nt][0];
                __half2 h1 = *(__half2*)&acc[mt][nt][1];
                float v00 = (__low2float(h0) + bx > 1.0f) ? 1.0f : 0.0f;
                float v01 = (__high2float(h0) + by > 1.0f) ? 1.0f : 0.0f;
                float v10 = (__low2float(h1) + bx > 1.0f) ? 1.0f : 0.0f;
                float v11 = (__high2float(h1) + by > 1.0f) ? 1.0f : 0.0f;
                *(float2*)(Cf + (size_t)r0 * Ntot + c) = make_float2(v00, v01);
                *(float2*)(Cf + (size_t)r1 * Ntot + c) = make_float2(v10, v11);
                if (WRITE_AUX) {
                    *(uint16_t*)(C8 + (size_t)r0 * Ntot + c) =
                        (uint16_t)((v00 != 0.0f ? FP8_ONE : 0u) |
                                   (v01 != 0.0f ? FP8_ONE << 8 : 0u));
                    *(uint16_t*)(C8 + (size_t)r1 * Ntot + c) =
                        (uint16_t)((v10 != 0.0f ? FP8_ONE : 0u) |
                                   (v11 != 0.0f ? FP8_ONE << 8 : 0u));
                    *(uint32_t*)(Cbf + (size_t)r0 * Ntot + c) =
                        (v00 != 0.0f ? BF16_ONE : 0u) |
                        (v01 != 0.0f ? BF16_ONE << 16 : 0u);
                    *(uint32_t*)(Cbf + (size_t)r1 * Ntot + c) =
                        (v10 != 0.0f ? BF16_ONE : 0u) |
                        (v11 != 0.0f ? BF16_ONE << 16 : 0u);
                }
            }
        }
    }
}

// ---------------------------------------------------------------------------
// Classifier via bf16 mma with exact W split (proven in R8):
//   C[b][l] = sum_h zbf[b][h] * (Whi[l][h] + Wlo[l][h])
// ---------------------------------------------------------------------------
#define CLF_T (128 * LDT)          // 10240 per tile
#define CLF_STG (3 * CLF_T)        // 30720 per stage (A, Whi, Wlo)
#define CLF_SMEM (3 * CLF_STG)     // 92160

__global__ __launch_bounds__(256) void clf_mma_kernel(
    const uint16_t* __restrict__ Z, const uint16_t* __restrict__ Whi,
    const uint16_t* __restrict__ Wlo, float* __restrict__ C) {
    constexpr int NCH = HV / 32;
    extern __shared__ __align__(16) uint8_t smem[];
    const uint32_t s0 = smem_u32(smem);

    const int tid  = threadIdx.x;
    const int lane = tid & 31;
    const int wid  = tid >> 5;
    const int wm   = wid & 3;
    const int wn   = wid >> 2;
    const int m0   = blockIdx.x * 128;

    const int gr = tid >> 2;
    const int gq = (tid & 3) * 16;
    const uint8_t* gA = (const uint8_t*)Z + ((size_t)(m0 + gr) * HV) * 2 + gq;
    const uint8_t* gH = (const uint8_t*)Whi + ((size_t)gr * HV) * 2 + gq;
    const uint8_t* gL = (const uint8_t*)Wlo + ((size_t)gr * HV) * 2 + gq;
    const uint32_t wA = s0 + gr * LDT + gq;
    const uint32_t wH = wA + CLF_T;
    const uint32_t wL = wH + CLF_T;

    const int a_row = wm * 32 + (lane & 7) + ((lane >> 3) & 1) * 8;
    const int a_qc  = (lane >> 4);
    const int b_row = wn * 64 + (lane & 7) + ((lane >> 4) & 1) * 8;
    const int b_qc  = (lane >> 3) & 1;
    const uint32_t rdA0 = s0 + a_row * LDT + a_qc * 16;
    const uint32_t rdH0 = s0 + CLF_T + b_row * LDT + b_qc * 16;
    const uint32_t rdL0 = rdH0 + CLF_T;

    float acc[2][8][4];
#pragma unroll
    for (int mt = 0; mt < 2; mt++)
#pragma unroll
        for (int nt = 0; nt < 8; nt++)
#pragma unroll
            for (int c = 0; c < 4; c++) acc[mt][nt][c] = 0.0f;

    auto issue = [&](int ch, int st) {
        const uint32_t off = st * CLF_STG;
        const int kc = ch * 64;
        cp16(wA + off, gA + kc);
        cp16(wA + off + 64 * LDT, gA + (size_t)64 * HV * 2 + kc);
        cp16(wH + off, gH + kc);
        cp16(wH + off + 64 * LDT, gH + (size_t)64 * HV * 2 + kc);
        cp16(wL + off, gL + kc);
        cp16(wL + off + 64 * LDT, gL + (size_t)64 * HV * 2 + kc);
        CP_COMMIT();
    };
    issue(0, 0);
    issue(1, 1);

    int st = 0, st_wr = 2;
    for (int ch = 0; ch < NCH; ch++) {
        if (ch + 1 < NCH) { CP_WAIT(1); } else { CP_WAIT(0); }
        __syncthreads();
        if (ch + 2 < NCH) {
            issue(ch + 2, st_wr);
            st_wr = (st_wr == 2) ? 0 : st_wr + 1;
        }
        const uint32_t rdA = rdA0 + st * CLF_STG;
        const uint32_t rdH = rdH0 + st * CLF_STG;
        const uint32_t rdL = rdL0 + st * CLF_STG;
#pragma unroll
        for (int ks = 0; ks < 2; ks++) {
            uint32_t af[2][4];
            ldm_x4(af[0], rdA + ks * 32);
            ldm_x4(af[1], rdA + 16 * LDT + ks * 32);
            uint32_t bh[8][2], bl[8][2];
#pragma unroll
            for (int nt2 = 0; nt2 < 4; nt2++) {
                uint32_t t[4];
                ldm_x4(t, rdH + nt2 * 16 * LDT + ks * 32);
                bh[2 * nt2][0] = t[0]; bh[2 * nt2][1] = t[1];
                bh[2 * nt2 + 1][0] = t[2]; bh[2 * nt2 + 1][1] = t[3];
                ldm_x4(t, rdL + nt2 * 16 * LDT + ks * 32);
                bl[2 * nt2][0] = t[0]; bl[2 * nt2][1] = t[1];
                bl[2 * nt2 + 1][0] = t[2]; bl[2 * nt2 + 1][1] = t[3];
            }
#pragma unroll
            for (int mt = 0; mt < 2; mt++)
#pragma unroll
                for (int nt = 0; nt < 8; nt++) {
                    mma_bf16(acc[mt][nt], af[mt], bh[nt][0], bh[nt][1]);
                    mma_bf16(acc[mt][nt], af[mt], bl[nt][0], bl[nt][1]);
                }
        }
        st = (st == 2) ? 0 : st + 1;
    }

    {
        const int g  = lane >> 2;
        const int tg = lane & 3;
        const int rbase = m0 + wm * 32 + g;
        const int cbase = wn * 64 + tg * 2;
#pragma unroll
        for (int mt = 0; mt < 2; mt++) {
            const int r0 = rbase + mt * 16;
            const int r1 = r0 + 8;
#pragma unroll
            for (int nt = 0; nt < 8; nt++) {
                const int c = cbase + nt * 8;
                *(float2*)(C + (size_t)r0 * LV + c) =
                    make_float2(acc[mt][nt][0], acc[mt][nt][1]);
                *(float2*)(C + (size_t)r1 * LV + c) =
                    make_float2(acc[mt][nt][2], acc[mt][nt][3]);
            }
        }
    }
}

// ---------------------------------------------------------------------------
// Launch.  Output layout: [output (B*D) | classification (B*L) | z (B*H)].
// ---------------------------------------------------------------------------
extern "C" void kernel_launch(void* const* d_in, const int* in_sizes, int n_in,
                              void* d_out, int out_size) {
    const float* x     = (const float*)d_in[0];
    const float* w     = (const float*)d_in[1];
    const float* bias0 = (const float*)d_in[2];
    const float* bias3 = (const float*)d_in[3];
    const float* clf   = (const float*)d_in[4];

    float* out        = (float*)d_out;
    float* out_output = out;
    float* out_class  = out + (size_t)BV * DV;
    float* out_z      = out + (size_t)BV * DV + (size_t)BV * LV;

    uint8_t *x8, *w8, *wT8, *z8;
    uint16_t *zbf, *whi, *wlo;
    cudaGetSymbolAddress((void**)&x8, g_x8);
    cudaGetSymbolAddress((void**)&w8, g_w8);
    cudaGetSymbolAddress((void**)&wT8, g_wT8);
    cudaGetSymbolAddress((void**)&z8, g_z8);
    cudaGetSymbolAddress((void**)&zbf, g_zbf);
    cudaGetSymbolAddress((void**)&whi, g_whi);
    cudaGetSymbolAddress((void**)&wlo, g_wlo);

    cudaFuncSetAttribute(fp8_mma_gemm_kernel<DV, true>,
                         cudaFuncAttributeMaxDynamicSharedMemorySize, GEMM_SMEM);
    cudaFuncSetAttribute(fp8_mma_gemm_kernel<HV, false>,
                         cudaFuncAttributeMaxDynamicSharedMemorySize, GEMM_SMEM);
    cudaFuncSetAttribute(clf_mma_kernel,
                         cudaFuncAttributeMaxDynamicSharedMemorySize, CLF_SMEM);

    // 1) conversions
    cvt_fp8_kernel<<<(BV * DV / 4) / 256, 256>>>(x, (uint32_t*)x8, BV * DV / 4);
    cvt_w_both_kernel<<<dim3(DV / 256, HV / 32), 256>>>(w, w8, wT8);
    cvt_wsplit_kernel<<<(LV * HV) / 256, 256>>>(clf, whi, wlo, LV * HV);

    // 2) GEMM1: z = (x @ wb^T + bias0 > 1); emits float + e4m3 + bf16 copies
    fp8_mma_gemm_kernel<DV, true>
        <<<dim3(HV / 256, BV / 128), 256, GEMM_SMEM>>>(x8, w8, bias0, out_z, z8,
                                                       zbf, HV);

    // 3) GEMM2: output = (z @ wb + bias3 > 1)
    fp8_mma_gemm_kernel<HV, false>
        <<<dim3(DV / 256, BV / 128), 256, GEMM_SMEM>>>(z8, wT8, bias3, out_output,
                                                       nullptr, nullptr, DV);

    // 4) classification = z @ clf^T  (bf16 split, fp32 accum)
    clf_mma_kernel<<<BV / 128, 256, CLF_SMEM>>>(zbf, whi, wlo, out_class);
}